// round 5
// baseline (speedup 1.0000x reference)
#include <cuda_runtime.h>
#include <cuda_bf16.h>

// Problem constants
#define BB 8
#define NPTS 16384
#define NG 512          // NUM_GROUPS
#define GS 32           // GROUP_SIZE
#define UK 512          // UPSCALE_K
#define CTX 256         // CONTEXT
#define R2 0.25f        // RADIUS^2

// Output layout (float32, flattened concat of the reference tuple)
#define OFF_GROUPS   0          // 8*256*32*4 = 262144
#define OFF_CENTERS  262144     // 8*256*4   = 8192
#define OFF_EMASK    270336     // 8*256     = 2048
#define OFF_PMASK    272384     // 8*256*32  = 65536

// ---------------- device scratch (no allocations allowed) ----------------
__device__ float4             g_centers[BB * NG];
__device__ float4             g_sorted[(size_t)BB * NPTS];        // Morton-binned pts {x,y,z,origidx}
__device__ unsigned long long g_cand[(size_t)BB * NG * UK];       // 16MB candidate keys
__device__ int                g_cand_cnt[BB * NG];
__device__ int                g_group_len[BB];

// exact (no fma contraction) squared distance, reduce order ((dx^2+dy^2)+dz^2)
__device__ __forceinline__ float d2_exact(float dx, float dy, float dz) {
    return __fadd_rn(__fadd_rn(__fmul_rn(dx, dx), __fmul_rn(dy, dy)), __fmul_rn(dz, dz));
}

__device__ __forceinline__ unsigned encf(float f) {       // order-preserving float->u32
    unsigned u = __float_as_uint(f);
    return (u & 0x80000000u) ? ~u : (u | 0x80000000u);
}
__device__ __forceinline__ float decf(unsigned e) {
    return __uint_as_float((e & 0x80000000u) ? (e & 0x7FFFFFFFu) : ~e);
}
__device__ __forceinline__ unsigned redux_max_u32(unsigned v) {
    unsigned r; asm("redux.sync.max.u32 %0, %1, 0xffffffff;" : "=r"(r) : "r"(v)); return r;
}
__device__ __forceinline__ unsigned redux_min_u32(unsigned v) {
    unsigned r; asm("redux.sync.min.u32 %0, %1, 0xffffffff;" : "=r"(r) : "r"(v)); return r;
}

// =====================================================================
// K0: Morton binning. 1 CTA/batch: 12-bit Morton cell (16^3 over [-4,4]),
// counting sort into g_sorted as {x,y,z,bitcast(orig_idx)}.
// (Order within a cell is atomic-nondeterministic; all downstream values
// are provably independent of bucket composition.)
// =====================================================================
#define CELLS 4096

__device__ __forceinline__ unsigned mpart(unsigned v) {   // spread 4 bits to 0,3,6,9
    v &= 15u;
    v = (v | (v << 4)) & 0x0C3u;
    v = (v | (v << 2)) & 0x249u;
    return v;
}

__global__ __launch_bounds__(512, 1)
void binning_kernel(const float4* __restrict__ pts) {
    __shared__ int s_h[CELLS];        // 16KB
    __shared__ int s_wtot[16];
    const int b = blockIdx.x, t = threadIdx.x;
    const int wid = t >> 5, lane = t & 31;
    const float4* __restrict__ P = pts + (size_t)b * NPTS;
    float4* __restrict__ S = g_sorted + (size_t)b * NPTS;

    for (int i = t; i < CELLS; i += 512) s_h[i] = 0;
    __syncthreads();

    int mycell[32];
#pragma unroll
    for (int i = 0; i < 32; i++) {
        int p = i * 512 + t;
        float4 v = P[p];
        int ix = min(15, max(0, (int)floorf((v.x + 4.0f) * 2.0f)));
        int iy = min(15, max(0, (int)floorf((v.y + 4.0f) * 2.0f)));
        int iz = min(15, max(0, (int)floorf((v.z + 4.0f) * 2.0f)));
        int cell = (int)(mpart(ix) | (mpart(iy) << 1) | (mpart(iz) << 2));
        mycell[i] = cell;
        atomicAdd(&s_h[cell], 1);
    }
    __syncthreads();

    // exclusive prefix over 4096 bins (8 bins/thread)
    int c[8]; int sum = 0;
#pragma unroll
    for (int j = 0; j < 8; j++) { c[j] = s_h[t * 8 + j]; }
#pragma unroll
    for (int j = 0; j < 8; j++) { int tmp = c[j]; c[j] = sum; sum += tmp; }
    int v = sum;
#pragma unroll
    for (int o = 1; o < 32; o <<= 1) {
        int u = __shfl_up_sync(0xffffffffu, v, o);
        if (lane >= o) v += u;
    }
    int wexcl = v - sum;
    if (lane == 31) s_wtot[wid] = v;
    __syncthreads();
    if (t == 0) {
        int run = 0;
#pragma unroll
        for (int w = 0; w < 16; w++) { int tmp = s_wtot[w]; s_wtot[w] = run; run += tmp; }
    }
    __syncthreads();
    int tbase = s_wtot[wid] + wexcl;
#pragma unroll
    for (int j = 0; j < 8; j++) s_h[t * 8 + j] = tbase + c[j];
    __syncthreads();

#pragma unroll
    for (int i = 0; i < 32; i++) {
        int p = i * 512 + t;
        float4 w = P[p];
        int pos = atomicAdd(&s_h[mycell[i]], 1);
        S[pos] = make_float4(w.x, w.y, w.z, __int_as_float(p));
    }
}

// =====================================================================
// K1: bucket-pruned FPS. 1 CTA/batch, 512 threads, 512 buckets x 32 pts.
// mind[16384] in smem; bucket bbox in registers (thread t owns bucket t).
// Per iter: lb-test -> compact dirty -> warp-per-bucket update (redux
// argmax) -> global argmax over 512 cached bucket keys. All sync local.
// =====================================================================
#define NBK 512

__global__ __launch_bounds__(512, 1)
void fps_pruned_kernel(const float4* __restrict__ pts, const int* __restrict__ lengths,
                       float* __restrict__ out_centers /* d_out + OFF_CENTERS */) {
    extern __shared__ float s_mind[];                 // [NPTS] 64KB dynamic
    __shared__ unsigned s_bek[NBK];                   // bucket key hi (orderable mind max)
    __shared__ unsigned s_bidx[NBK];                  // bucket key lo (orig idx of argmax)
    __shared__ float    s_bmax[NBK];                  // bucket max mind (float)
    __shared__ float    s_bx[NBK], s_by[NBK], s_bz[NBK];
    __shared__ int      s_dirty[NBK];
    __shared__ int      s_nd;
    __shared__ unsigned long long s_red[16];
    __shared__ unsigned long long s_wink;
    __shared__ float4   s_win;
    __shared__ int      s_cidx[NG];

    const int b = blockIdx.x, t = threadIdx.x;
    const int wid = t >> 5, lane = t & 31;
    const int len = lengths[b];
    const float4* __restrict__ S = g_sorted + (size_t)b * NPTS;
    const float4* __restrict__ P = pts + (size_t)b * NPTS;

    // init: warp w handles buckets [w*32, w*32+32); at j==lane keep own bbox
    float rlox = 0, rloy = 0, rloz = 0, rhix = 0, rhiy = 0, rhiz = 0;
#pragma unroll 4
    for (int j = 0; j < 32; j++) {
        int d = wid * 32 + j;
        int p = d * 32 + lane;
        float4 v = S[p];
        int orig = __float_as_int(v.w);
        float m0 = (orig < len) ? 1e10f : -1e30f;
        s_mind[p] = m0;
        float xlo = decf(redux_min_u32(encf(v.x)));
        float xhi = decf(redux_max_u32(encf(v.x)));
        float ylo = decf(redux_min_u32(encf(v.y)));
        float yhi = decf(redux_max_u32(encf(v.y)));
        float zlo = decf(redux_min_u32(encf(v.z)));
        float zhi = decf(redux_max_u32(encf(v.z)));
        if (j == lane) { rlox = xlo; rhix = xhi; rloy = ylo; rhiy = yhi; rloz = zlo; rhiz = zhi; }
        unsigned em = encf(m0);
        unsigned wm = redux_max_u32(em);
        unsigned wi = redux_min_u32((em == wm) ? (unsigned)orig : 0xFFFFFFFFu);
        if (lane == 0) {
            s_bek[d] = wm; s_bidx[d] = wi; s_bmax[d] = decf(wm);
        }
    }
    if (t == 0) {
        float4 v0 = __ldg(&P[0]);
        s_win = make_float4(v0.x, v0.y, v0.z, 0.0f);
        s_cidx[0] = 0;
        s_nd = 0;
        g_group_len[b] = 0;
    }
    __syncthreads();

    for (int k = 1; k < NG; k++) {
        const float4 w = s_win;
        const float cx = w.x, cy = w.y, cz = w.z;

        // (1) lb test for own bucket + warp-aggregated compaction
        {
            float gx = fmaxf(fmaxf(rlox - cx, cx - rhix), 0.0f);
            float gy = fmaxf(fmaxf(rloy - cy, cy - rhiy), 0.0f);
            float gz = fmaxf(fmaxf(rloz - cz, cz - rhiz), 0.0f);
            float lb2 = d2_exact(gx, gy, gz) * 0.999998f;   // conservative margin
            bool dirty = lb2 < s_bmax[t];
            unsigned m = __ballot_sync(0xffffffffu, dirty);
            int nb = __popc(m);
            int base = 0;
            if (lane == 0 && nb) base = atomicAdd(&s_nd, nb);
            base = __shfl_sync(0xffffffffu, base, 0);
            if (dirty) s_dirty[base + __popc(m & ((1u << lane) - 1u))] = t;
        }
        __syncthreads();                                    // bar1

        // (2) warp-per-bucket update of dirty buckets
        const int nd = s_nd;
        for (int j = wid; j < nd; j += 16) {
            int d = s_dirty[j];
            int p = d * 32 + lane;
            float4 v = __ldg(&S[p]);
            float m = s_mind[p];
            float d2 = d2_exact(v.x - cx, v.y - cy, v.z - cz);
            m = fminf(m, d2);
            s_mind[p] = m;
            unsigned em = encf(m);
            unsigned wm = redux_max_u32(em);
            int orig = __float_as_int(v.w);
            unsigned wi = redux_min_u32((em == wm) ? (unsigned)orig : 0xFFFFFFFFu);
            if (em == wm && (unsigned)orig == wi) {         // unique winner lane
                s_bek[d] = wm; s_bidx[d] = wi; s_bmax[d] = m;
                s_bx[d] = v.x; s_by[d] = v.y; s_bz[d] = v.z;
            }
        }
        __syncthreads();                                    // bar2

        // (3) global argmax over 512 bucket keys
        unsigned long long ukey =
            ((unsigned long long)s_bek[t] << 32) | (0xFFFFFFFFu - s_bidx[t]);
        unsigned long long key = ukey;
#pragma unroll
        for (int o = 16; o > 0; o >>= 1) {
            unsigned long long ok = __shfl_down_sync(0xffffffffu, key, o);
            key = (ok > key) ? ok : key;
        }
        if (lane == 0) s_red[wid] = key;
        if (t == 0) s_nd = 0;                               // reset for next iter
        __syncthreads();                                    // bar3
        if (t == 0) {
            unsigned long long bk = s_red[0];
#pragma unroll
            for (int j = 1; j < 16; j++) { unsigned long long kk = s_red[j]; if (kk > bk) bk = kk; }
            s_wink = bk;
        }
        __syncthreads();                                    // bar4
        if (ukey == s_wink) {                               // unique owner thread
            s_win = make_float4(s_bx[t], s_by[t], s_bz[t], 0.0f);
            s_cidx[k] = (int)s_bidx[t];
        }
        __syncthreads();                                    // bar5
    }

    // tail: gather centers (all 4 channels incl. energy) by orig idx
    {
        int p = s_cidx[t];
        float4 v = __ldg(&P[p]);
        g_centers[b * NG + t] = v;
        if (t < CTX) ((float4*)out_centers)[b * CTX + t] = v;
    }
}

// =====================================================================
// K2: ball query. Warp owns 4 centers; streams all points (L1/L2-hot),
// ballot+popc gives exact in-index-order candidate rank (first 512 kept).
// Key packs (orderable energy bits << 32) | (0xFFFFFFFF - idx).
// =====================================================================
#define CPW 4
#define BQ_T 256   // 8 warps -> 32 centers per CTA; grid (16, 8)

__global__ __launch_bounds__(BQ_T, 4)
void ballquery_kernel(const float4* __restrict__ pts, const int* __restrict__ lengths) {
    const int b = blockIdx.y;
    const int w = threadIdx.x >> 5, lane = threadIdx.x & 31;
    const int cbase = blockIdx.x * 32 + w * CPW;
    const int len = lengths[b];
    const float4* __restrict__ P = pts + (size_t)b * NPTS;

    float cx[CPW], cy[CPW], cz[CPW];
    int cnt[CPW];
#pragma unroll
    for (int c = 0; c < CPW; c++) {
        float4 cc = g_centers[b * NG + cbase + c];
        cx[c] = cc.x; cy[c] = cc.y; cz[c] = cc.z; cnt[c] = 0;
    }
    unsigned long long* __restrict__ buf = g_cand + (size_t)(b * NG + cbase) * UK;

    const int lim = (len + 31) & ~31;
    const unsigned lt = (1u << lane) - 1u;

    for (int p0 = 0; p0 < lim; p0 += 32) {
        int p = p0 + lane;
        float4 v = __ldg(&P[p]);
        bool inlen = (p < len);
        unsigned eb = __float_as_uint(v.w);
        unsigned ekey = (eb & 0x80000000u) ? ~eb : (eb | 0x80000000u);
        unsigned long long pk = ((unsigned long long)ekey << 32) | (unsigned)(0xFFFFFFFFu - (unsigned)p);

#pragma unroll
        for (int c = 0; c < CPW; c++) {
            if (cnt[c] < UK) {   // warp-uniform
                float dx = v.x - cx[c], dy = v.y - cy[c], dz = v.z - cz[c];
                float d2 = d2_exact(dx, dy, dz);
                bool pred = inlen && (d2 < R2);
                unsigned m = __ballot_sync(0xffffffffu, pred);
                int rnk = cnt[c] + __popc(m & lt);
                if (pred && rnk < UK) buf[(size_t)c * UK + rnk] = pk;
                cnt[c] = min(UK, cnt[c] + __popc(m));
            }
        }
        if (cnt[0] >= UK && cnt[1] >= UK && cnt[2] >= UK && cnt[3] >= UK) break;
    }
    if (lane == 0) {
#pragma unroll
        for (int c = 0; c < CPW; c++) g_cand_cnt[b * NG + cbase + c] = cnt[c];
    }
}

// =====================================================================
// K3: per-group adaptive bitonic (M = next pow2 >= cnt, min 32) descending
// sort of candidate keys, then emit. grid (512, 8), 256 threads.
// =====================================================================
__global__ __launch_bounds__(256, 8)
void sort_emit_kernel(const float4* __restrict__ pts,
                      float* __restrict__ out_groups /* d_out */,
                      float* __restrict__ out_pmask  /* d_out + OFF_PMASK */) {
    const int gi = blockIdx.x;
    const int b  = blockIdx.y;
    const int g  = b * NG + gi;
    const int t  = threadIdx.x;

    __shared__ unsigned long long s[UK];
    const int cnt = g_cand_cnt[g];
    const unsigned long long* __restrict__ src = g_cand + (size_t)g * UK;

    int M = GS;
    while (M < cnt) M <<= 1;                       // 32..512, CTA-uniform

    for (int i = t; i < M; i += 256)
        s[i] = (i < cnt) ? src[i] : 0ull;

    for (int kk = 2; kk <= M; kk <<= 1) {
        for (int j = kk >> 1; j > 0; j >>= 1) {
            __syncthreads();
            for (int e = t; e < M; e += 256) {
                int l = e ^ j;
                if (l > e) {
                    unsigned long long a = s[e], c = s[l];
                    bool dsc = ((e & kk) == 0);
                    bool sw = dsc ? (a < c) : (a > c);
                    if (sw) { s[e] = c; s[l] = a; }
                }
            }
        }
    }
    __syncthreads();

    const int pl = min(cnt, GS);
    if (t == 0 && cnt >= GS) atomicAdd(&g_group_len[b], 1);

    if (gi < CTX) {
        if (t < GS * 4) {
            int slot = t >> 2, ch = t & 3;
            int ss = (slot < pl) ? slot : 0;
            unsigned p = 0xFFFFFFFFu - (unsigned)(s[ss] & 0xFFFFFFFFull);
            const float* pp = (const float*)(pts + ((size_t)b * NPTS + p));
            out_groups[(((size_t)(b * CTX + gi)) * GS + slot) * 4 + ch] = pp[ch];
        } else if (t < GS * 4 + GS) {
            int slot = t - GS * 4;
            out_pmask[(size_t)(b * CTX + gi) * GS + slot] = (slot < pl) ? 1.0f : 0.0f;
        }
    }
}

// =====================================================================
// K4: embedding mask
// =====================================================================
__global__ void emask_kernel(float* __restrict__ em) {
    int b = blockIdx.x, t = threadIdx.x;
    em[b * CTX + t] = (t < g_group_len[b]) ? 1.0f : 0.0f;
}

// =====================================================================
extern "C" void kernel_launch(void* const* d_in, const int* in_sizes, int n_in,
                              void* d_out, int out_size) {
    const float4* pts = (const float4*)d_in[0];   // (8,16384,4) f32
    const int*   lens = (const int*)d_in[1];      // (8,)
    float* out = (float*)d_out;

    cudaFuncSetAttribute(fps_pruned_kernel,
                         cudaFuncAttributeMaxDynamicSharedMemorySize, NPTS * (int)sizeof(float));

    binning_kernel<<<BB, 512>>>(pts);
    fps_pruned_kernel<<<BB, 512, NPTS * sizeof(float)>>>(pts, lens, out + OFF_CENTERS);
    ballquery_kernel<<<dim3(16, BB), BQ_T>>>(pts, lens);
    sort_emit_kernel<<<dim3(NG, BB), 256>>>(pts, out + OFF_GROUPS, out + OFF_PMASK);
    emask_kernel<<<BB, CTX>>>(out + OFF_EMASK);
}

// round 6
// speedup vs baseline: 1.2336x; 1.2336x over previous
#include <cuda_runtime.h>
#include <cuda_bf16.h>

// Problem constants
#define BB 8
#define NPTS 16384
#define NG 512          // NUM_GROUPS
#define GS 32           // GROUP_SIZE
#define UK 512          // UPSCALE_K
#define CTX 256         // CONTEXT
#define R2 0.25f        // RADIUS^2

// Output layout (float32, flattened concat of the reference tuple)
#define OFF_GROUPS   0          // 8*256*32*4 = 262144
#define OFF_CENTERS  262144     // 8*256*4   = 8192
#define OFF_EMASK    270336     // 8*256     = 2048
#define OFF_PMASK    272384     // 8*256*32  = 65536

// ---------------- device scratch (no allocations allowed) ----------------
__device__ float4             g_centers[BB * NG];
__device__ unsigned long long g_cand[(size_t)BB * NG * UK];       // 16MB candidate keys
__device__ int                g_cand_cnt[BB * NG];
__device__ int                g_group_len[BB];

// exact (no fma contraction) squared distance, reduce order ((dx^2+dy^2)+dz^2)
__device__ __forceinline__ float d2_exact(float dx, float dy, float dz) {
    return __fadd_rn(__fadd_rn(__fmul_rn(dx, dx), __fmul_rn(dy, dy)), __fmul_rn(dz, dz));
}

__device__ __forceinline__ unsigned encf(float f) {       // order-preserving float->u32
    unsigned u = __float_as_uint(f);
    return (u & 0x80000000u) ? ~u : (u | 0x80000000u);
}
__device__ __forceinline__ unsigned redux_max_u32(unsigned v) {
    unsigned r; asm("redux.sync.max.u32 %0, %1, 0xffffffff;" : "=r"(r) : "r"(v)); return r;
}
__device__ __forceinline__ unsigned redux_min_u32(unsigned v) {
    unsigned r; asm("redux.sync.min.u32 %0, %1, 0xffffffff;" : "=r"(r) : "r"(v)); return r;
}

// packed f32x2 helpers (two independent fp32 RN lanes — bit-exact vs scalar)
#define PACK2(o, lo, hi)  asm("mov.b64 %0, {%1, %2};" : "=l"(o) : "f"(lo), "f"(hi))
#define UNPACK2(lo, hi, i) asm("mov.b64 {%0, %1}, %2;" : "=f"(lo), "=f"(hi) : "l"(i))
#define ADDX2(o, a, b)    asm("add.rn.f32x2 %0, %1, %2;" : "=l"(o) : "l"(a), "l"(b))
#define MULX2(o, a, b)    asm("mul.rn.f32x2 %0, %1, %2;" : "=l"(o) : "l"(a), "l"(b))

// =====================================================================
// K1: dense FPS, f32x2-packed. 1 CTA/batch, 512 threads, 16 point-PAIRS
// per thread. x,y packed in registers; z in smem (LDS.64/pair); smem also
// keeps an xyz copy for O(1) winner-coordinate fetch. 2 barriers/iter.
// =====================================================================
#define FPS_T 512
#define PAIRS 16
#define FPS_SMEM (NPTS * 8 + NPTS * 4)   // sxy[NPTS] float2 (128KB) + z pairs (64KB)

__global__ void __launch_bounds__(FPS_T, 1)
fps_kernel(const float4* __restrict__ pts, const int* __restrict__ lengths,
           float* __restrict__ out_centers /* d_out + OFF_CENTERS */) {
    extern __shared__ float smem[];
    float2* __restrict__ sxy = (float2*)smem;              // [NPTS] by point
    float2* __restrict__ szp = (float2*)(smem + 2 * NPTS); // [NPTS/2] z pairs
    __shared__ unsigned long long s_wk[16];
    __shared__ float4 s_win;
    __shared__ int    s_cidx[NG];

    const int b = blockIdx.x, t = threadIdx.x;
    const int wid = t >> 5, lane = t & 31;
    const float4* __restrict__ P = pts + (size_t)b * NPTS;
    const int len = lengths[b];

    unsigned long long X[PAIRS], Y[PAIRS];
    float mind[2 * PAIRS];

#pragma unroll
    for (int i = 0; i < PAIRS; i++) {
        int q = i * FPS_T + t;
        int p0 = 2 * q, p1 = 2 * q + 1;
        float4 v0 = P[p0], v1 = P[p1];
        bool va = (p0 < len), vb = (p1 < len);
        float x0 = va ? v0.x : 1e18f, y0 = va ? v0.y : 1e18f, z0 = va ? v0.z : 1e18f;
        float x1 = vb ? v1.x : 1e18f, y1 = vb ? v1.y : 1e18f, z1 = vb ? v1.z : 1e18f;
        PACK2(X[i], x0, x1);
        PACK2(Y[i], y0, y1);
        sxy[p0] = make_float2(x0, y0);
        sxy[p1] = make_float2(x1, y1);
        szp[q]  = make_float2(z0, z1);
        mind[2 * i]     = va ? 1e10f : -1e30f;
        mind[2 * i + 1] = vb ? 1e10f : -1e30f;
    }
    if (t == 0) {
        float4 v0 = __ldg(&P[0]);
        s_win = make_float4(v0.x, v0.y, v0.z, 0.0f);
        s_cidx[0] = 0;
        g_group_len[b] = 0;
    }
    __syncthreads();

    for (int k = 1; k < NG; k++) {
        const float4 w = s_win;
        unsigned long long nCx, nCy, nCz;
        PACK2(nCx, -w.x, -w.x);
        PACK2(nCy, -w.y, -w.y);
        PACK2(nCz, -w.z, -w.z);

        float fm = -1e30f;
#pragma unroll
        for (int i = 0; i < PAIRS; i++) {
            int q = i * FPS_T + t;
            float2 zz = szp[q];
            unsigned long long Zp, dx, dy, dz, sx, sy, sz, s1, d2p;
            PACK2(Zp, zz.x, zz.y);
            ADDX2(dx, X[i], nCx);           // x - cx  (== add of negated, IEEE exact)
            ADDX2(dy, Y[i], nCy);
            ADDX2(dz, Zp,  nCz);
            MULX2(sx, dx, dx);
            MULX2(sy, dy, dy);
            MULX2(sz, dz, dz);
            ADDX2(s1, sx, sy);              // (dx^2 + dy^2)
            ADDX2(d2p, s1, sz);             // ... + dz^2   (same order as scalar)
            float lo, hi;
            UNPACK2(lo, hi, d2p);
            float m0 = fminf(mind[2 * i],     lo);
            float m1 = fminf(mind[2 * i + 1], hi);
            mind[2 * i] = m0; mind[2 * i + 1] = m1;
            fm = fmaxf(fm, fmaxf(m0, m1));
        }

        // warp argmax: max value (redux), then min point index among matches
        unsigned ek = encf(fm);
        unsigned wm = redux_max_u32(ek);
        unsigned mybp = 0xFFFFFFFFu;
        if (ek == wm) {                      // predicated rescan (winning lanes only)
#pragma unroll
            for (int i = PAIRS - 1; i >= 0; i--) {
                int q = i * FPS_T + t;
                if (mind[2 * i + 1] == fm) mybp = (unsigned)(2 * q + 1);
                if (mind[2 * i]     == fm) mybp = (unsigned)(2 * q);
            }
        }
        unsigned wi = redux_min_u32(mybp);
        if (lane == 0)
            s_wk[wid] = ((unsigned long long)wm << 32) | (0xFFFFFFFFu - wi);
        __syncthreads();                     // bar1

        if (t < 32) {
            unsigned long long key = (lane < 16) ? s_wk[lane] : 0ull;
#pragma unroll
            for (int o = 8; o > 0; o >>= 1) {
                unsigned long long ok = __shfl_down_sync(0xffffffffu, key, o);
                key = (ok > key) ? ok : key;
            }
            if (lane == 0) {
                int wpt = (int)(0xFFFFFFFFu - (unsigned)(key & 0xFFFFFFFFull));
                float2 xy = sxy[wpt];
                float2 z2 = szp[wpt >> 1];
                float wz = (wpt & 1) ? z2.y : z2.x;
                s_win = make_float4(xy.x, xy.y, wz, 0.0f);
                s_cidx[k] = wpt;
            }
        }
        __syncthreads();                     // bar2
    }

    // tail: gather centers (all 4 channels incl. energy)
    {
        int p = s_cidx[t];
        float4 v = __ldg(&P[p]);
        g_centers[b * NG + t] = v;
        if (t < CTX) ((float4*)out_centers)[b * CTX + t] = v;
    }
}

// =====================================================================
// K2: ball query. Warp owns 4 centers; streams all points (L1/L2-hot),
// ballot+popc gives exact in-index-order candidate rank (first 512 kept).
// Key packs (orderable energy bits << 32) | (0xFFFFFFFF - idx).
// =====================================================================
#define CPW 4
#define BQ_T 256   // 8 warps -> 32 centers per CTA; grid (16, 8)

__global__ __launch_bounds__(BQ_T, 4)
void ballquery_kernel(const float4* __restrict__ pts, const int* __restrict__ lengths) {
    const int b = blockIdx.y;
    const int w = threadIdx.x >> 5, lane = threadIdx.x & 31;
    const int cbase = blockIdx.x * 32 + w * CPW;
    const int len = lengths[b];
    const float4* __restrict__ P = pts + (size_t)b * NPTS;

    float cx[CPW], cy[CPW], cz[CPW];
    int cnt[CPW];
#pragma unroll
    for (int c = 0; c < CPW; c++) {
        float4 cc = g_centers[b * NG + cbase + c];
        cx[c] = cc.x; cy[c] = cc.y; cz[c] = cc.z; cnt[c] = 0;
    }
    unsigned long long* __restrict__ buf = g_cand + (size_t)(b * NG + cbase) * UK;

    const int lim = (len + 31) & ~31;
    const unsigned lt = (1u << lane) - 1u;

    for (int p0 = 0; p0 < lim; p0 += 32) {
        int p = p0 + lane;
        float4 v = __ldg(&P[p]);
        bool inlen = (p < len);
        unsigned eb = __float_as_uint(v.w);
        unsigned ekey = (eb & 0x80000000u) ? ~eb : (eb | 0x80000000u);
        unsigned long long pk = ((unsigned long long)ekey << 32) | (unsigned)(0xFFFFFFFFu - (unsigned)p);

#pragma unroll
        for (int c = 0; c < CPW; c++) {
            if (cnt[c] < UK) {   // warp-uniform
                float dx = v.x - cx[c], dy = v.y - cy[c], dz = v.z - cz[c];
                float d2 = d2_exact(dx, dy, dz);
                bool pred = inlen && (d2 < R2);
                unsigned m = __ballot_sync(0xffffffffu, pred);
                int rnk = cnt[c] + __popc(m & lt);
                if (pred && rnk < UK) buf[(size_t)c * UK + rnk] = pk;
                cnt[c] = min(UK, cnt[c] + __popc(m));
            }
        }
        if (cnt[0] >= UK && cnt[1] >= UK && cnt[2] >= UK && cnt[3] >= UK) break;
    }
    if (lane == 0) {
#pragma unroll
        for (int c = 0; c < CPW; c++) g_cand_cnt[b * NG + cbase + c] = cnt[c];
    }
}

// =====================================================================
// K3: per-group adaptive bitonic (M = next pow2 >= cnt, min 32) descending
// sort of candidate keys, then emit. grid (512, 8), 256 threads.
// =====================================================================
__global__ __launch_bounds__(256, 8)
void sort_emit_kernel(const float4* __restrict__ pts,
                      float* __restrict__ out_groups /* d_out */,
                      float* __restrict__ out_pmask  /* d_out + OFF_PMASK */) {
    const int gi = blockIdx.x;
    const int b  = blockIdx.y;
    const int g  = b * NG + gi;
    const int t  = threadIdx.x;

    __shared__ unsigned long long s[UK];
    const int cnt = g_cand_cnt[g];
    const unsigned long long* __restrict__ src = g_cand + (size_t)g * UK;

    int M = GS;
    while (M < cnt) M <<= 1;                       // 32..512, CTA-uniform

    for (int i = t; i < M; i += 256)
        s[i] = (i < cnt) ? src[i] : 0ull;

    for (int kk = 2; kk <= M; kk <<= 1) {
        for (int j = kk >> 1; j > 0; j >>= 1) {
            __syncthreads();
            for (int e = t; e < M; e += 256) {
                int l = e ^ j;
                if (l > e) {
                    unsigned long long a = s[e], c = s[l];
                    bool dsc = ((e & kk) == 0);
                    bool sw = dsc ? (a < c) : (a > c);
                    if (sw) { s[e] = c; s[l] = a; }
                }
            }
        }
    }
    __syncthreads();

    const int pl = min(cnt, GS);
    if (t == 0 && cnt >= GS) atomicAdd(&g_group_len[b], 1);

    if (gi < CTX) {
        if (t < GS * 4) {
            int slot = t >> 2, ch = t & 3;
            int ss = (slot < pl) ? slot : 0;
            unsigned p = 0xFFFFFFFFu - (unsigned)(s[ss] & 0xFFFFFFFFull);
            const float* pp = (const float*)(pts + ((size_t)b * NPTS + p));
            out_groups[(((size_t)(b * CTX + gi)) * GS + slot) * 4 + ch] = pp[ch];
        } else if (t < GS * 4 + GS) {
            int slot = t - GS * 4;
            out_pmask[(size_t)(b * CTX + gi) * GS + slot] = (slot < pl) ? 1.0f : 0.0f;
        }
    }
}

// =====================================================================
// K4: embedding mask
// =====================================================================
__global__ void emask_kernel(float* __restrict__ em) {
    int b = blockIdx.x, t = threadIdx.x;
    em[b * CTX + t] = (t < g_group_len[b]) ? 1.0f : 0.0f;
}

// =====================================================================
extern "C" void kernel_launch(void* const* d_in, const int* in_sizes, int n_in,
                              void* d_out, int out_size) {
    const float4* pts = (const float4*)d_in[0];   // (8,16384,4) f32
    const int*   lens = (const int*)d_in[1];      // (8,)
    float* out = (float*)d_out;

    cudaFuncSetAttribute(fps_kernel,
                         cudaFuncAttributeMaxDynamicSharedMemorySize, FPS_SMEM);

    fps_kernel<<<BB, FPS_T, FPS_SMEM>>>(pts, lens, out + OFF_CENTERS);
    ballquery_kernel<<<dim3(16, BB), BQ_T>>>(pts, lens);
    sort_emit_kernel<<<dim3(NG, BB), 256>>>(pts, out + OFF_GROUPS, out + OFF_PMASK);
    emask_kernel<<<BB, CTX>>>(out + OFF_EMASK);
}